// round 7
// baseline (speedup 1.0000x reference)
#include <cuda_runtime.h>
#include <math.h>

#define DIM   4096
#define NH    32
#define HD    128
#define SEQ   4096
#define BATCH 16

typedef unsigned long long u64;

// Scratch (allocation-free)
__device__ float g_q  [BATCH * DIM];
__device__ float g_kn [BATCH * DIM];
__device__ float g_vn [BATCH * DIM];
__device__ float g_att[BATCH * DIM];
// split-attention partials: per (bh, split): m, l, o[128]
__device__ float g_pm [BATCH * NH * 2];
__device__ float g_pl [BATCH * NH * 2];
__device__ float g_po [BATCH * NH * 2 * HD];

// ---------------- packed fp32x2 helpers ----------------
__device__ __forceinline__ u64 ffma2(u64 a, u64 b, u64 c) {
    u64 d; asm("fma.rn.f32x2 %0, %1, %2, %3;" : "=l"(d) : "l"(a), "l"(b), "l"(c)); return d;
}
__device__ __forceinline__ void unpack2(u64 v, float& lo, float& hi) {
    asm("mov.b64 {%0, %1}, %2;" : "=f"(lo), "=f"(hi) : "l"(v));
}

#define ROW_U2 (DIM / 4)   // ulonglong2 (16B) elements per 4096-float row

// ---------------------------------------------------------------------------
// Skinny GEMM: out[b][j] = dot(x[b,:], W[j,:]).  Warp tile: 4 W rows x 8
// batches, K split over lanes, k-pairs packed in f32x2.
// W loads are double-buffered in registers (load kb+1 while computing kb)
// so the per-iteration DRAM-latency scoreboard wait disappears; the only
// wait left is x@L2 (~250cyc), covered by the fma stream of 4 warps/SMSP.
// ---------------------------------------------------------------------------
__device__ __forceinline__ void gemm_warp(const float* __restrict__ x,
                                          const float* __restrict__ Wrows,
                                          float* __restrict__ out,
                                          int j0, int bh /* 0 or 8 */) {
    int lane = threadIdx.x & 31;

    u64 acc[4][8];
#pragma unroll
    for (int r = 0; r < 4; r++)
#pragma unroll
        for (int b = 0; b < 8; b++) acc[r][b] = 0ull;

    const ulonglong2* W2 = reinterpret_cast<const ulonglong2*>(Wrows);
    const ulonglong2* X2 = reinterpret_cast<const ulonglong2*>(x) + (size_t)bh * ROW_U2;

    // prologue: W chunk 0
    ulonglong2 w0 = __ldcs(W2 + 0 * ROW_U2 + lane);
    ulonglong2 w1 = __ldcs(W2 + 1 * ROW_U2 + lane);
    ulonglong2 w2 = __ldcs(W2 + 2 * ROW_U2 + lane);
    ulonglong2 w3 = __ldcs(W2 + 3 * ROW_U2 + lane);

#pragma unroll 1
    for (int kb = 0; kb < DIM / 128; kb++) {
        int fidx = kb * 32 + lane;

        // x loads: all 8 issued up front (hit L2, ~250cyc)
        ulonglong2 x0 = X2[0 * ROW_U2 + fidx];
        ulonglong2 x1 = X2[1 * ROW_U2 + fidx];
        ulonglong2 x2 = X2[2 * ROW_U2 + fidx];
        ulonglong2 x3 = X2[3 * ROW_U2 + fidx];
        ulonglong2 x4 = X2[4 * ROW_U2 + fidx];
        ulonglong2 x5 = X2[5 * ROW_U2 + fidx];
        ulonglong2 x6 = X2[6 * ROW_U2 + fidx];
        ulonglong2 x7 = X2[7 * ROW_U2 + fidx];

        // W prefetch for next iteration (DRAM latency hidden by this
        // iteration's 64 FFMA2 + the other warps)
        ulonglong2 nw0, nw1, nw2, nw3;
        if (kb < DIM / 128 - 1) {
            int nidx = fidx + 32;
            nw0 = __ldcs(W2 + 0 * ROW_U2 + nidx);
            nw1 = __ldcs(W2 + 1 * ROW_U2 + nidx);
            nw2 = __ldcs(W2 + 2 * ROW_U2 + nidx);
            nw3 = __ldcs(W2 + 3 * ROW_U2 + nidx);
        }

#pragma unroll
        for (int b = 0; b < 8; b++) {
            ulonglong2 xv = (b == 0) ? x0 : (b == 1) ? x1 : (b == 2) ? x2 :
                            (b == 3) ? x3 : (b == 4) ? x4 : (b == 5) ? x5 :
                            (b == 6) ? x6 : x7;
            acc[0][b] = ffma2(w0.x, xv.x, acc[0][b]);
            acc[0][b] = ffma2(w0.y, xv.y, acc[0][b]);
            acc[1][b] = ffma2(w1.x, xv.x, acc[1][b]);
            acc[1][b] = ffma2(w1.y, xv.y, acc[1][b]);
            acc[2][b] = ffma2(w2.x, xv.x, acc[2][b]);
            acc[2][b] = ffma2(w2.y, xv.y, acc[2][b]);
            acc[3][b] = ffma2(w3.x, xv.x, acc[3][b]);
            acc[3][b] = ffma2(w3.y, xv.y, acc[3][b]);
        }

        w0 = nw0; w1 = nw1; w2 = nw2; w3 = nw3;
    }

    // collapse k-pairs, then butterfly over lanes
#pragma unroll
    for (int r = 0; r < 4; r++)
#pragma unroll
        for (int b = 0; b < 8; b++) {
            float lo, hi;
            unpack2(acc[r][b], lo, hi);
            float v = lo + hi;
#pragma unroll
            for (int off = 16; off; off >>= 1)
                v += __shfl_xor_sync(0xffffffffu, v, off);
            if (lane == 0)
                out[(size_t)(bh + b) * DIM + j0 + r] = v;
        }
}

// QKV: 768 blocks x 256 threads. Block = 16 consecutive fused rows
// (4 row-groups x 2 batch-half warps). Blocks never straddle a matrix.
__global__ void __launch_bounds__(256, 2) qkv_gemm(const float* __restrict__ x,
                                                   const float* __restrict__ wq,
                                                   const float* __restrict__ wk,
                                                   const float* __restrict__ wv) {
    int w  = threadIdx.x >> 5;
    int jg = blockIdx.x * 16 + (w >> 1) * 4;
    int bh = (w & 1) * 8;
    int which = jg >> 12;
    int jl    = jg & (DIM - 1);
    const float* W   = (which == 0) ? wq  : (which == 1) ? wk   : wv;
    float*       out = (which == 0) ? g_q : (which == 1) ? g_kn : g_vn;
    gemm_warp(x, W + (size_t)jl * DIM, out, jl, bh);
}

// O projection: 256 blocks x 256 threads, consumes g_att (native layout).
__global__ void __launch_bounds__(256, 2) oproj_gemm(const float* __restrict__ wo,
                                                     float* __restrict__ out) {
    int w  = threadIdx.x >> 5;
    int j  = blockIdx.x * 16 + (w >> 1) * 4;
    int bh = (w & 1) * 8;
    gemm_warp(g_att, wo + (size_t)j * DIM, out, j, bh);
}

// ---------------------------------------------------------------------------
// Decode attention, seq-split-2: 1024 blocks (bh = blk>>1, split = blk&1),
// 8 warps. Each warp: 4-row unroll (r, r+8, r+16, r+24 stepping 32) over its
// 2048-row half -> 8 loads in flight, 4 independent shuffle chains.
// Block writes unnormalized partial (m, l, o[128]) to global scratch.
// ---------------------------------------------------------------------------
__global__ void __launch_bounds__(256) decode_attn(const float* __restrict__ kc,
                                                   const float* __restrict__ vc) {
    int bh   = blockIdx.x >> 1;
    int s    = blockIdx.x & 1;
    int b    = bh >> 5;
    int h    = bh & 31;
    int tid  = threadIdx.x;
    int w    = tid >> 5;
    int lane = tid & 31;

    const float4* K = reinterpret_cast<const float4*>(kc + (size_t)bh * SEQ * HD);
    const float4* V = reinterpret_cast<const float4*>(vc + (size_t)bh * SEQ * HD);

    float4 q4 = reinterpret_cast<const float4*>(g_q + b * DIM + h * HD)[lane];
    const float scale = 0.08838834764831845f;   // 1/sqrt(128)

    float  m = -INFINITY;
    float  l = 0.f;
    float4 o = make_float4(0.f, 0.f, 0.f, 0.f);

    int base = s * (SEQ / 2);
    for (int i = 0; i < (SEQ / 2) / 32; i++) {
        int r0 = base + i * 32 + w;
        float4 k0 = __ldcs(K + (size_t)(r0     ) * (HD / 4) + lane);
        float4 k1 = __ldcs(K + (size_t)(r0 +  8) * (HD / 4) + lane);
        float4 k2 = __ldcs(K + (size_t)(r0 + 16) * (HD / 4) + lane);
        float4 k3 = __ldcs(K + (size_t)(r0 + 24) * (HD / 4) + lane);
        float4 v0 = __ldcs(V + (size_t)(r0     ) * (HD / 4) + lane);
        float4 v1 = __ldcs(V + (size_t)(r0 +  8) * (HD / 4) + lane);
        float4 v2 = __ldcs(V + (size_t)(r0 + 16) * (HD / 4) + lane);
        float4 v3 = __ldcs(V + (size_t)(r0 + 24) * (HD / 4) + lane);

        float s0 = q4.x * k0.x + q4.y * k0.y + q4.z * k0.z + q4.w * k0.w;
        float s1 = q4.x * k1.x + q4.y * k1.y + q4.z * k1.z + q4.w * k1.w;
        float s2 = q4.x * k2.x + q4.y * k2.y + q4.z * k2.z + q4.w * k2.w;
        float s3 = q4.x * k3.x + q4.y * k3.y + q4.z * k3.z + q4.w * k3.w;
#pragma unroll
        for (int off = 16; off; off >>= 1) {
            s0 += __shfl_xor_sync(0xffffffffu, s0, off);
            s1 += __shfl_xor_sync(0xffffffffu, s1, off);
            s2 += __shfl_xor_sync(0xffffffffu, s2, off);
            s3 += __shfl_xor_sync(0xffffffffu, s3, off);
        }
        s0 *= scale; s1 *= scale; s2 *= scale; s3 *= scale;

        float nm = fmaxf(fmaxf(m, fmaxf(s0, s1)), fmaxf(s2, s3));
        float c  = __expf(m - nm);
        float p0 = __expf(s0 - nm);
        float p1 = __expf(s1 - nm);
        float p2 = __expf(s2 - nm);
        float p3 = __expf(s3 - nm);
        l   = l * c + p0 + p1 + p2 + p3;
        o.x = o.x * c + p0 * v0.x + p1 * v1.x + p2 * v2.x + p3 * v3.x;
        o.y = o.y * c + p0 * v0.y + p1 * v1.y + p2 * v2.y + p3 * v3.y;
        o.z = o.z * c + p0 * v0.z + p1 * v1.z + p2 * v2.z + p3 * v3.z;
        o.w = o.w * c + p0 * v0.w + p1 * v1.w + p2 * v2.w + p3 * v3.w;
        m   = nm;
    }

    // new token (row SEQ) handled once, by split 1 / warp 0
    if (s == 1 && w == 0) {
        const float4* Kn = reinterpret_cast<const float4*>(g_kn + b * DIM + h * HD);
        const float4* Vn = reinterpret_cast<const float4*>(g_vn + b * DIM + h * HD);
        float4 kv = Kn[lane];
        float4 vv = Vn[lane];
        float sc = q4.x * kv.x + q4.y * kv.y + q4.z * kv.z + q4.w * kv.w;
#pragma unroll
        for (int off = 16; off; off >>= 1)
            sc += __shfl_xor_sync(0xffffffffu, sc, off);
        sc *= scale;
        float nm = fmaxf(m, sc);
        float c  = __expf(m - nm);
        float p  = __expf(sc - nm);
        l   = l * c + p;
        o.x = o.x * c + p * vv.x;
        o.y = o.y * c + p * vv.y;
        o.z = o.z * c + p * vv.z;
        o.w = o.w * c + p * vv.w;
        m   = nm;
    }

    // merge 8 warp-partials -> block partial (unnormalized) to scratch
    __shared__ float  sm[8];
    __shared__ float  sl[8];
    __shared__ float4 so[8][32];
    so[w][lane] = o;
    if (lane == 0) { sm[w] = m; sl[w] = l; }
    __syncthreads();

    if (tid < HD) {
        int d = tid;
        float gm = sm[0];
#pragma unroll
        for (int i = 1; i < 8; i++) gm = fmaxf(gm, sm[i]);
        const float* sof = reinterpret_cast<const float*>(so);
        float num = 0.f, den = 0.f;
#pragma unroll
        for (int i = 0; i < 8; i++) {
            float f = __expf(sm[i] - gm);
            num += f * sof[i * HD + d];
            den += f * sl[i];
        }
        int ps = bh * 2 + s;
        g_po[(size_t)ps * HD + d] = num;
        if (d == 0) { g_pm[ps] = gm; g_pl[ps] = den; }
    }
}

// Merge the two splits: 512 blocks x 128 threads.
__global__ void attn_merge() {
    int bh = blockIdx.x;
    int d  = threadIdx.x;
    float m0 = g_pm[bh * 2 + 0], m1 = g_pm[bh * 2 + 1];
    float gm = fmaxf(m0, m1);
    float e0 = __expf(m0 - gm), e1 = __expf(m1 - gm);
    float den = e0 * g_pl[bh * 2 + 0] + e1 * g_pl[bh * 2 + 1];
    float num = e0 * g_po[(size_t)(bh * 2 + 0) * HD + d]
              + e1 * g_po[(size_t)(bh * 2 + 1) * HD + d];
    int b = bh >> 5, h = bh & 31;
    g_att[b * DIM + h * HD + d] = num / den;
}

// ---------------------------------------------------------------------------
extern "C" void kernel_launch(void* const* d_in, const int* in_sizes, int n_in,
                              void* d_out, int out_size) {
    const float* x  = (const float*)d_in[0];
    const float* kc = (const float*)d_in[1];
    const float* vc = (const float*)d_in[2];
    const float* wq = (const float*)d_in[3];
    const float* wk = (const float*)d_in[4];
    const float* wv = (const float*)d_in[5];
    const float* wo = (const float*)d_in[6];
    float* out = (float*)d_out;

    qkv_gemm  <<<3 * DIM / 16, 256>>>(x, wq, wk, wv);
    decode_attn<<<BATCH * NH * 2, 256>>>(kc, vc);
    attn_merge<<<BATCH * NH, HD>>>();
    oproj_gemm<<<DIM / 16, 256>>>(wo, out);
}